// round 5
// baseline (speedup 1.0000x reference)
#include <cuda_runtime.h>
#include <math.h>

#define NG   4
#define NB   6
#define NF   8
#define NFRR 256
#define NACT 5
#define BTOT 32768

// Precomputed factorization of relation similarity:
// sim[g,n,m]*16 = feat_n^T M_g feat_m + vt_g.feat_n + vp_g.feat_m + c_g
__device__ float g_M[NG][NF * NF];
__device__ float g_vt[NG][NF];
__device__ float g_vp[NG][NF];
__device__ float g_c[NG];

__global__ void precompute_kernel(const float* __restrict__ Wt,
                                  const float* __restrict__ bt,
                                  const float* __restrict__ Wp,
                                  const float* __restrict__ bp)
{
    int g   = blockIdx.x;
    int tid = threadIdx.x;                 // 256 threads
    const float* wt  = Wt + g * NFRR * NF;
    const float* wp  = Wp + g * NFRR * NF;
    const float* btg = bt + g * NFRR;
    const float* bpg = bp + g * NFRR;
    __shared__ float red[256];

    // M[e][f] = sum_r wt[r][e] * wp[r][f]
    int ef = tid & 63, q = tid >> 6;
    int e  = ef >> 3,  f = ef & 7;
    float acc = 0.f;
#pragma unroll 8
    for (int r = q * 64; r < q * 64 + 64; r++)
        acc = fmaf(wt[r * NF + e], wp[r * NF + f], acc);
    red[tid] = acc;
    __syncthreads();
    if (q == 0)
        g_M[g][ef] = (red[ef] + red[64 + ef]) + (red[128 + ef] + red[192 + ef]);
    __syncthreads();

    float a2 = 0.f;
    if (tid < 64) {
        int ff = tid & 7, s = tid >> 3;
#pragma unroll 8
        for (int r = s * 32; r < s * 32 + 32; r++)
            a2 = fmaf(wt[r * NF + ff], bpg[r], a2);
        red[tid] = a2;
    } else if (tid < 128) {
        int id = tid - 64, ff = id & 7, s = id >> 3;
#pragma unroll 8
        for (int r = s * 32; r < s * 32 + 32; r++)
            a2 = fmaf(btg[r], wp[r * NF + ff], a2);
        red[tid] = a2;
    } else if (tid < 160) {
        int s = tid - 128;
#pragma unroll
        for (int r = s * 8; r < s * 8 + 8; r++)
            a2 = fmaf(btg[r], bpg[r], a2);
        red[tid] = a2;
    }
    __syncthreads();
    if (tid < 8) {
        float sm = 0.f;
        for (int s = 0; s < 8; s++) sm += red[s * 8 + tid];
        g_vt[g][tid] = sm;
    } else if (tid < 16) {
        int ff = tid - 8;
        float sm = 0.f;
        for (int s = 0; s < 8; s++) sm += red[64 + s * 8 + ff];
        g_vp[g][ff] = sm;
    } else if (tid == 16) {
        float sm = 0.f;
        for (int k = 0; k < 32; k++) sm += red[128 + k];
        g_c[g] = sm;
    }
}

// dual-accumulator 8-dot against a register array wr[8]
#define DOT8_DUAL(res, xv, wr, init)                                     \
    do {                                                                 \
        float _a0 = fmaf((xv)[0], (wr)[0], (init));                      \
        float _a1 = (xv)[1] * (wr)[1];                                   \
        _a0 = fmaf((xv)[2], (wr)[2], _a0);                               \
        _a1 = fmaf((xv)[3], (wr)[3], _a1);                               \
        _a0 = fmaf((xv)[4], (wr)[4], _a0);                               \
        _a1 = fmaf((xv)[5], (wr)[5], _a1);                               \
        _a0 = fmaf((xv)[6], (wr)[6], _a0);                               \
        _a1 = fmaf((xv)[7], (wr)[7], _a1);                               \
        (res) = _a0 + _a1;                                               \
    } while (0)

#define LOAD8(dst, src)                                                  \
    do {                                                                 \
        float4 _v0 = ((const float4*)(src))[0];                          \
        float4 _v1 = ((const float4*)(src))[1];                          \
        (dst)[0] = _v0.x; (dst)[1] = _v0.y; (dst)[2] = _v0.z;            \
        (dst)[3] = _v0.w; (dst)[4] = _v1.x; (dst)[5] = _v1.y;            \
        (dst)[6] = _v1.z; (dst)[7] = _v1.w;                              \
    } while (0)

// 4 threads per batch: sub = (nhalf<<1)|ghalf.
//   ghalf selects graphs {2*ghalf, 2*ghalf+1}; nhalf selects rows {0..2}/{3..5}.
// Reductions: gsum over ghalf partner (xor 1), max-pool over nhalf (xor 2).
__global__ __launch_bounds__(128, 4) void gcn_main4(
    const float* __restrict__ X,     // [B,6,8]
    const float* __restrict__ P,     // [B,6,2]
    const float* __restrict__ Wext,  // [8,8]
    const float* __restrict__ bext,  // [8]
    const float* __restrict__ Wgcn,  // [4,8,8]
    const float* __restrict__ Wact,  // [5,8]
    const float* __restrict__ bact,  // [5]
    float* __restrict__ out)         // [B,5]
{
    __shared__ __align__(16) float sWext[64];
    __shared__ __align__(16) float sM[NG][64];
    __shared__ __align__(16) float sWgcn[NG][64];
    __shared__ __align__(16) float svt[NG][NF];
    __shared__ __align__(16) float svp[NG][NF];
    __shared__ __align__(16) float sWact[40];
    __shared__ float sbext[NF], sbact[NACT], sc[NG];

    int tid = threadIdx.x;
    if (tid < 64) sWext[tid] = Wext[tid];
    else if (tid < 104) sWact[tid - 64] = Wact[tid - 64];
    else if (tid < 112) sbext[tid - 104] = bext[tid - 104];
    else if (tid < 117) sbact[tid - 112] = bact[tid - 112];
    else if (tid < 121) sc[tid - 117] = g_c[tid - 117];
    for (int i = tid; i < 256; i += 128) {
        ((float*)sM)[i]    = ((const float*)g_M)[i];
        ((float*)sWgcn)[i] = Wgcn[i];
    }
    if (tid < 32) {
        ((float*)svt)[tid] = ((const float*)g_vt)[tid];
        ((float*)svp)[tid] = ((const float*)g_vp)[tid];
    }

    int t     = blockIdx.x * 128 + tid;
    int b     = t >> 2;
    int sub   = t & 3;
    int ghalf = sub & 1;
    int nhalf = sub >> 1;
    int n0    = nhalf * 3;

    // ---- pairwise distance mask for own 3 rows (exact R1 op sequence) ----
    const float4* P4 = (const float4*)(P + b * 12);
    float4 p0 = P4[0], p1 = P4[1], p2 = P4[2];
    float px[NB] = {p0.x, p0.z, p1.x, p1.z, p2.x, p2.z};
    float py[NB] = {p0.y, p0.w, p1.y, p1.w, p2.y, p2.w};
    float rr[NB];
#pragma unroll
    for (int n = 0; n < NB; n++)
        rr[n] = __fmaf_rn(py[n], py[n], __fmul_rn(px[n], px[n]));
    unsigned rowm[3];
#pragma unroll
    for (int i = 0; i < 3; i++) {
        int n = n0 + i;
        unsigned rm = 0;
#pragma unroll
        for (int m = 0; m < NB; m++) {
            float dot = __fmaf_rn(py[n], py[m], __fmul_rn(px[n], px[m]));
            float d2  = __fadd_rn(__fsub_rn(rr[n], __fmul_rn(2.0f, dot)), rr[m]);
            if (__fsqrt_rn(d2) > 4.0f) rm |= 1u << m;
        }
        rowm[i] = rm;
    }

    __syncthreads();   // weights staged

    // ---- feature extension, processed in row-pairs to bound live regs ----
    const float4* X4 = (const float4*)(X + b * 48);
    float feat[NB][NF];
#pragma unroll
    for (int npair = 0; npair < 3; npair++) {
        float xa[NF], xb[NF];
        LOAD8(xa, &X4[npair * 4]);       // row 2*npair
        LOAD8(xb, &X4[npair * 4 + 2]);   // row 2*npair+1
#pragma unroll
        for (int f = 0; f < NF; f++) {
            float wr[NF];
            LOAD8(wr, &sWext[f * 8]);
            float r0, r1;
            DOT8_DUAL(r0, xa, wr, sbext[f]);
            DOT8_DUAL(r1, xb, wr, sbext[f]);
            feat[npair * 2][f]     = fmaxf(r0, 0.0f);
            feat[npair * 2 + 1][f] = fmaxf(r1, 0.0f);
        }
    }

    // ---- 2 relation graphs for this lane ----
    float gsum[3][NF];
#pragma unroll
    for (int i = 0; i < 3; i++)
#pragma unroll
        for (int f = 0; f < NF; f++) gsum[i][f] = 0.0f;

#pragma unroll
    for (int gg = 0; gg < 2; gg++) {
        int g = ghalf * 2 + gg;

        float sphi[NB];
        {
            float vpr[NF];
            LOAD8(vpr, svp[g]);
#pragma unroll
            for (int m = 0; m < NB; m++)
                DOT8_DUAL(sphi[m], feat[m], vpr, 0.0f);
        }
        float vtr[NF];
        LOAD8(vtr, svt[g]);
        float cg = sc[g];

#pragma unroll
        for (int i = 0; i < 3; i++) {
            int n = n0 + i;

            // tt[f] = sum_e feat[n][e] * M[e][f]  (ILP-8 across f)
            float tt[NF];
#pragma unroll
            for (int f = 0; f < NF; f++) tt[f] = 0.f;
#pragma unroll
            for (int e = 0; e < NF; e++) {
                float mr[NF];
                LOAD8(mr, &sM[g][e * 8]);
                float fv = feat[n][e];
#pragma unroll
                for (int f = 0; f < NF; f++) tt[f] = fmaf(fv, mr[f], tt[f]);
            }
            float st;
            DOT8_DUAL(st, feat[n], vtr, cg);

            float s[NB];
#pragma unroll
            for (int m = 0; m < NB; m++) {
                float a;
                DOT8_DUAL(a, tt, feat[m], st + sphi[m]);
                s[m] = a * 0.0625f;   // / sqrt(256)
            }

            unsigned rm = rowm[i];
            float mx = -3.402823466e38f;
#pragma unroll
            for (int m = 0; m < NB; m++)
                if (!((rm >> m) & 1u)) mx = fmaxf(mx, s[m]);
            float w[NB];
            float ps = 0.f;
#pragma unroll
            for (int m = 0; m < NB; m++) {
                float e_ = ((rm >> m) & 1u) ? 0.0f : __expf(s[m] - mx);
                w[m] = e_; ps += e_;
            }
            float inv = 1.0f / ps;

            float agg[NF];
#pragma unroll
            for (int f = 0; f < NF; f++) agg[f] = 0.f;
#pragma unroll
            for (int m = 0; m < NB; m++) {
                float wv = w[m] * inv;
#pragma unroll
                for (int f = 0; f < NF; f++)
                    agg[f] = fmaf(wv, feat[m][f], agg[f]);
            }

#pragma unroll
            for (int o = 0; o < NF; o++) {
                float wr[NF];
                LOAD8(wr, &sWgcn[g][o * 8]);
                float a;
                DOT8_DUAL(a, agg, wr, 0.0f);
                gsum[i][o] += fmaxf(a, 0.0f);
            }
        }
    }

    // ---- reduce gsum over the ghalf partner (lane xor 1) ----
#pragma unroll
    for (int i = 0; i < 3; i++)
#pragma unroll
        for (int f = 0; f < NF; f++)
            gsum[i][f] += __shfl_xor_sync(0xffffffffu, gsum[i][f], 1);

    // ---- residual + max-pool over own 3 boxes ----
    float pl[NF];
#pragma unroll
    for (int f = 0; f < NF; f++) pl[f] = -3.402823466e38f;
#pragma unroll
    for (int i = 0; i < 3; i++) {
        int n = n0 + i;
        float xv[NF];
        LOAD8(xv, &X4[n * 2]);
#pragma unroll
        for (int f = 0; f < NF; f++)
            pl[f] = fmaxf(pl[f], fmaf(gsum[i][f], 0.25f, xv[f]));
    }

    // ---- combine the two n-halves (lane xor 2) ----
#pragma unroll
    for (int f = 0; f < NF; f++) {
        float o = __shfl_xor_sync(0xffffffffu, pl[f], 2);
        pl[f] = fmaxf(pl[f], o);
    }

    // ---- activity head (lane sub==0 writes) ----
    if (sub == 0) {
        float* ob = out + b * NACT;
#pragma unroll
        for (int a = 0; a < NACT; a++) {
            float wr[NF];
            LOAD8(wr, &sWact[a * 8]);
            float acc;
            DOT8_DUAL(acc, pl, wr, sbact[a]);
            ob[a] = acc;
        }
    }
}

extern "C" void kernel_launch(void* const* d_in, const int* in_sizes, int n_in,
                              void* d_out, int out_size)
{
    const float* X    = (const float*)d_in[0];
    const float* P    = (const float*)d_in[1];
    const float* Wext = (const float*)d_in[2];
    const float* bext = (const float*)d_in[3];
    const float* Wt   = (const float*)d_in[4];
    const float* bt   = (const float*)d_in[5];
    const float* Wp   = (const float*)d_in[6];
    const float* bp   = (const float*)d_in[7];
    const float* Wgcn = (const float*)d_in[8];
    const float* Wact = (const float*)d_in[9];
    const float* bact = (const float*)d_in[10];

    precompute_kernel<<<NG, 256>>>(Wt, bt, Wp, bp);
    gcn_main4<<<BTOT * 4 / 128, 128>>>(X, P, Wext, bext, Wgcn, Wact, bact,
                                       (float*)d_out);
}